// round 16
// baseline (speedup 1.0000x reference)
#include <cuda_runtime.h>
#include <math.h>
#include <stdint.h>

#define TB 1024
#define HD 1024
#define NHQ 16
#define NHKV 4
#define DH 64
#define SEQ 512
#define NB 2
#define NE 8
#define ID 4096

// ---- scratch ----
__device__ float g_h [TB*HD + 16];
__device__ float g_q [TB*NHQ*DH + 16];
__device__ float g_k [TB*NHKV*DH + 16];
__device__ float g_v [TB*NHKV*DH + 16];
__device__ float g_sc[(size_t)NB*NHQ*SEQ*SEQ + 16];
__device__ float g_ao[TB*NHQ*DH + 16];
__device__ float g_x2[TB*HD + 16];
__device__ float g_t [TB*HD + 16];
__device__ int   g_cnt[NE];
__device__ int   g_rows[NE*TB];
__device__ int   g_se[TB*2];
__device__ int   g_sr[TB*2];
__device__ float g_sp[TB*2];
__device__ float g_act[(size_t)NE*TB*ID + 16];
__device__ float g_dn [(size_t)NE*TB*HD + 16];

// ---- primitives ----
__device__ __forceinline__ uint32_t tf32cvt(float x){
    uint32_t u; asm("cvt.rna.tf32.f32 %0, %1;" : "=r"(u) : "f"(x)); return u;
}
__device__ __forceinline__ uint4 cvt4(float4 v){
    return make_uint4(tf32cvt(v.x), tf32cvt(v.y), tf32cvt(v.z), tf32cvt(v.w));
}
__device__ __forceinline__ void mma8(float* d, const uint32_t* a, uint32_t b0, uint32_t b1){
    asm volatile("mma.sync.aligned.m16n8k8.row.col.f32.tf32.tf32.f32 "
        "{%0,%1,%2,%3},{%4,%5,%6,%7},{%8,%9},{%0,%1,%2,%3};"
        : "+f"(d[0]),"+f"(d[1]),"+f"(d[2]),"+f"(d[3])
        : "r"(a[0]),"r"(a[1]),"r"(a[2]),"r"(a[3]),"r"(b0),"r"(b1));
}

// ============ 256-thr mainloop (scores / pv) ============
template<int NI, bool BTRANS>
__device__ __forceinline__ void mm_loop(float (&acc)[4][NI][4],
    const float* __restrict__ A, int lda, int rm,
    const float* __restrict__ B, int ldb, int bn, int K,
    uint32_t* As, uint32_t* Bs)
{
    const int BPITCH = BTRANS ? 20 : NI*32 + 8;
    const int ASTG = 128*20;
    const int BSTG = BTRANS ? 128*20 : 16*BPITCH;
    const int tid = threadIdx.x, lane = tid & 31, warp = tid >> 5;
    const int wm = warp >> 2, wn = warp & 3, q = lane >> 2, s = lane & 3;
#pragma unroll
    for (int i = 0; i < 4; i++)
#pragma unroll
        for (int j = 0; j < NI; j++)
#pragma unroll
            for (int r = 0; r < 4; r++) acc[i][j][r] = 0.f;

    const int f0 = tid, f1 = tid + 256;
    const int ar0 = f0 >> 2, ac0 = (f0 & 3) << 2;
    const int ar1 = f1 >> 2, ac1 = (f1 & 3) << 2;
    const float* pa0 = A + (size_t)(rm + ar0)*lda + ac0;
    const float* pa1 = A + (size_t)(rm + ar1)*lda + ac1;

    const float* pb0; const float* pb1 = nullptr;
    int bs0, bs1 = 0;
    if (BTRANS){
        pb0 = B + (size_t)(bn + ar0)*ldb + ac0;
        pb1 = B + (size_t)(bn + ar1)*ldb + ac1;
        bs0 = ar0*20 + ac0; bs1 = ar1*20 + ac1;
    } else {
        const int bk0 = tid >> 4, bc0 = (tid & 15) << 2;
        pb0 = B + (size_t)bk0*ldb + bn + bc0;
        bs0 = bk0*BPITCH + bc0;
    }

    float4 va0, va1, vb0, vb1;
    auto gload = [&](int k0){
        va0 = *(const float4*)(pa0 + k0);
        va1 = *(const float4*)(pa1 + k0);
        if (BTRANS){
            vb0 = *(const float4*)(pb0 + k0);
            vb1 = *(const float4*)(pb1 + k0);
        } else {
            vb0 = *(const float4*)(pb0 + (size_t)k0*ldb);
        }
    };
    auto stage = [&](int buf){
        uint32_t* dA = As + buf*ASTG;
        *(uint4*)(dA + ar0*20 + ac0) = cvt4(va0);
        *(uint4*)(dA + ar1*20 + ac1) = cvt4(va1);
        uint32_t* dB = Bs + buf*BSTG;
        *(uint4*)(dB + bs0) = cvt4(vb0);
        if (BTRANS) *(uint4*)(dB + bs1) = cvt4(vb1);
    };

    gload(0); stage(0); __syncthreads();
    const int nst = K >> 4;
    for (int st = 0; st < nst; st++){
        const int buf = st & 1;
        const bool more = (st + 1 < nst);
        if (more) gload((st + 1) << 4);
        const uint32_t* pA = As + buf*ASTG;
        const uint32_t* pB = Bs + buf*BSTG;
#pragma unroll
        for (int kk = 0; kk < 2; kk++){
            const int c0 = kk*8 + s;
            uint32_t af[4][4];
#pragma unroll
            for (int im = 0; im < 4; im++){
                const int r0 = wm*64 + im*16 + q;
                af[im][0]=pA[r0*20+c0];   af[im][1]=pA[(r0+8)*20+c0];
                af[im][2]=pA[r0*20+c0+4]; af[im][3]=pA[(r0+8)*20+c0+4];
            }
#pragma unroll
            for (int in = 0; in < NI; in++){
                const int nn = wn*(NI*8) + in*8 + q;
                uint32_t b0, b1;
                if (BTRANS){ b0 = pB[nn*20+c0]; b1 = pB[nn*20+c0+4]; }
                else       { b0 = pB[c0*BPITCH+nn]; b1 = pB[(c0+4)*BPITCH+nn]; }
#pragma unroll
                for (int im = 0; im < 4; im++) mma8(acc[im][in], af[im], b0, b1);
            }
        }
        if (more) stage(buf ^ 1);
        __syncthreads();
    }
}

// ====== single-B, 128 thr, tile 128x64, warp 64x32, 2-stage ======
__device__ __forceinline__ void mm1_128(float (&acc)[4][4][4],
    const float* __restrict__ A, int lda, int rm,
    const float* __restrict__ B, int ldb, int bn, int K,
    uint32_t* As, uint32_t* Bs)
{
    const int ASTG = 128*20, BSTG = 16*72;
    const int tid = threadIdx.x, lane = tid & 31, warp = tid >> 5;
    const int wm = warp >> 1, wn = warp & 1, q = lane >> 2, s = lane & 3;
#pragma unroll
    for (int i = 0; i < 4; i++)
#pragma unroll
        for (int j = 0; j < 4; j++)
#pragma unroll
            for (int r = 0; r < 4; r++) acc[i][j][r] = 0.f;

    int ar[4], ac[4];
    const float* pa[4];
#pragma unroll
    for (int i = 0; i < 4; i++){
        const int f = tid + i*128;
        ar[i] = f >> 2; ac[i] = (f & 3) << 2;
        pa[i] = A + (size_t)(rm + ar[i])*lda + ac[i];
    }
    int bs[2];
    const float* pb[2];
#pragma unroll
    for (int i = 0; i < 2; i++){
        const int f = tid + i*128;
        const int bk = f >> 4, bc = (f & 15) << 2;
        bs[i] = bk*72 + bc;
        pb[i] = B + (size_t)bk*ldb + bn + bc;
    }

    float4 va[4], wb[2];
    auto gload = [&](int k0){
#pragma unroll
        for (int i = 0; i < 4; i++) va[i] = *(const float4*)(pa[i] + k0);
#pragma unroll
        for (int i = 0; i < 2; i++) wb[i] = *(const float4*)(pb[i] + (size_t)k0*ldb);
    };
    auto stage = [&](int buf){
        uint32_t* dA = As + buf*ASTG;
#pragma unroll
        for (int i = 0; i < 4; i++) *(uint4*)(dA + ar[i]*20 + ac[i]) = cvt4(va[i]);
        uint32_t* dB = Bs + buf*BSTG;
#pragma unroll
        for (int i = 0; i < 2; i++) *(uint4*)(dB + bs[i]) = cvt4(wb[i]);
    };

    gload(0); stage(0); __syncthreads();
    const int nst = K >> 4;
    for (int st = 0; st < nst; st++){
        const int buf = st & 1;
        const bool more = (st + 1 < nst);
        if (more) gload((st + 1) << 4);
        const uint32_t* pA = As + buf*ASTG;
        const uint32_t* pB = Bs + buf*BSTG;
#pragma unroll
        for (int kk = 0; kk < 2; kk++){
            const int c0 = kk*8 + s;
            uint32_t af[4][4];
#pragma unroll
            for (int im = 0; im < 4; im++){
                const int r0 = wm*64 + im*16 + q;
                af[im][0]=pA[r0*20+c0];   af[im][1]=pA[(r0+8)*20+c0];
                af[im][2]=pA[r0*20+c0+4]; af[im][3]=pA[(r0+8)*20+c0+4];
            }
#pragma unroll
            for (int in = 0; in < 4; in++){
                const int nn = wn*32 + in*8 + q;
                uint32_t b0 = pB[c0*72+nn], b1 = pB[(c0+4)*72+nn];
#pragma unroll
                for (int im = 0; im < 4; im++) mma8(acc[im][in], af[im], b0, b1);
            }
        }
        if (more) stage(buf ^ 1);
        __syncthreads();
    }
}

// ===== dual-B mainloop, 256 thr, tile 128x64, warp 32x32 (4m x 2n) =====
__device__ __forceinline__ void mm_dual256(float (&a1)[2][4][4], float (&a2)[2][4][4],
    const float* __restrict__ A, int lda, const int* srow,
    const float* __restrict__ B1, const float* __restrict__ B2,
    int ldb, int bn, int K,
    uint32_t* As, uint32_t* B1s, uint32_t* B2s)
{
    const int ASTG = 128*20, BSTG = 16*72;
    const int tid = threadIdx.x, lane = tid & 31, warp = tid >> 5;
    const int wm = warp >> 1, wn = warp & 1, q = lane >> 2, s = lane & 3;
#pragma unroll
    for (int i = 0; i < 2; i++)
#pragma unroll
        for (int j = 0; j < 4; j++)
#pragma unroll
            for (int r = 0; r < 4; r++){ a1[i][j][r]=0.f; a2[i][j][r]=0.f; }

    int ar[2], ac[2];
    const float* pa[2];
#pragma unroll
    for (int i = 0; i < 2; i++){
        const int f = tid + i*256;
        ar[i] = f >> 2; ac[i] = (f & 3) << 2;
        pa[i] = A + (size_t)srow[ar[i]]*lda + ac[i];
    }
    const int bk = tid >> 4, bc = (tid & 15) << 2;
    const int bso = bk*72 + bc;
    const float* p1 = B1 + (size_t)bk*ldb + bn + bc;
    const float* p2 = B2 + (size_t)bk*ldb + bn + bc;

    float4 va[2], w1, w2;
    auto gload = [&](int k0){
#pragma unroll
        for (int i = 0; i < 2; i++) va[i] = *(const float4*)(pa[i] + k0);
        w1 = *(const float4*)(p1 + (size_t)k0*ldb);
        w2 = *(const float4*)(p2 + (size_t)k0*ldb);
    };
    auto stage = [&](int buf){
        uint32_t* dA = As + buf*ASTG;
#pragma unroll
        for (int i = 0; i < 2; i++)
            *(uint4*)(dA + ar[i]*20 + ac[i]) = cvt4(va[i]);
        *(uint4*)(B1s + buf*BSTG + bso) = cvt4(w1);
        *(uint4*)(B2s + buf*BSTG + bso) = cvt4(w2);
    };

    gload(0); stage(0); __syncthreads();
    const int nst = K >> 4;
    for (int st = 0; st < nst; st++){
        const int buf = st & 1;
        const bool more = (st + 1 < nst);
        if (more) gload((st + 1) << 4);
        const uint32_t* pA = As + buf*ASTG;
        const uint32_t* q1 = B1s + buf*BSTG;
        const uint32_t* q2 = B2s + buf*BSTG;
#pragma unroll
        for (int kk = 0; kk < 2; kk++){
            const int c0 = kk*8 + s;
            uint32_t af[2][4];
#pragma unroll
            for (int im = 0; im < 2; im++){
                const int r0 = wm*32 + im*16 + q;
                af[im][0]=pA[r0*20+c0];   af[im][1]=pA[(r0+8)*20+c0];
                af[im][2]=pA[r0*20+c0+4]; af[im][3]=pA[(r0+8)*20+c0+4];
            }
#pragma unroll
            for (int in = 0; in < 4; in++){
                const int nn = wn*32 + in*8 + q;
                uint32_t b0 = q1[c0*72+nn], b1 = q1[(c0+4)*72+nn];
                uint32_t c0b = q2[c0*72+nn], c1b = q2[(c0+4)*72+nn];
#pragma unroll
                for (int im = 0; im < 2; im++){
                    mma8(a1[im][in], af[im], b0, b1);
                    mma8(a2[im][in], af[im], c0b, c1b);
                }
            }
        }
        if (more) stage(buf ^ 1);
        __syncthreads();
    }
}

// ============ 4-warp (128 thr) warp-64x64 mainloop for k_down ============
__device__ __forceinline__ void mm_down(float (&acc)[4][8][4],
    const float* __restrict__ A, int lda, int rm,
    const float* __restrict__ B, int ldb, int bn, int K,
    uint32_t* As, uint32_t* Bs)
{
    const int ASTG = 128*20, BSTG = 16*136;
    const int tid = threadIdx.x, lane = tid & 31, warp = tid >> 5;
    const int wm = warp >> 1, wn = warp & 1, q = lane >> 2, s = lane & 3;
#pragma unroll
    for (int i = 0; i < 4; i++)
#pragma unroll
        for (int j = 0; j < 8; j++)
#pragma unroll
            for (int r = 0; r < 4; r++) acc[i][j][r] = 0.f;

    int ar[4], ac[4], bs[4];
    const float* pa[4]; const float* pb[4];
#pragma unroll
    for (int i = 0; i < 4; i++){
        const int f = tid + i*128;
        ar[i] = f >> 2; ac[i] = (f & 3) << 2;
        pa[i] = A + (size_t)(rm + ar[i])*lda + ac[i];
        const int bk = f >> 5, bc = (f & 31) << 2;
        bs[i] = bk*136 + bc;
        pb[i] = B + (size_t)bk*ldb + bn + bc;
    }

    float4 va[4], vb[4];
    auto gload = [&](int k0){
#pragma unroll
        for (int i = 0; i < 4; i++){
            va[i] = *(const float4*)(pa[i] + k0);
            vb[i] = *(const float4*)(pb[i] + (size_t)k0*ldb);
        }
    };
    auto stage = [&](int buf){
        uint32_t* dA = As + buf*ASTG;
        uint32_t* dB = Bs + buf*BSTG;
#pragma unroll
        for (int i = 0; i < 4; i++){
            *(uint4*)(dA + ar[i]*20 + ac[i]) = cvt4(va[i]);
            *(uint4*)(dB + bs[i]) = cvt4(vb[i]);
        }
    };

    gload(0); stage(0); __syncthreads();
    const int nst = K >> 4;
    for (int st = 0; st < nst; st++){
        const int buf = st & 1;
        const bool more = (st + 1 < nst);
        if (more) gload((st + 1) << 4);
        const uint32_t* pA = As + buf*ASTG;
        const uint32_t* pB = Bs + buf*BSTG;
#pragma unroll
        for (int kk = 0; kk < 2; kk++){
            const int c0 = kk*8 + s;
            uint32_t af[4][4];
#pragma unroll
            for (int im = 0; im < 4; im++){
                const int r0 = wm*64 + im*16 + q;
                af[im][0]=pA[r0*20+c0];   af[im][1]=pA[(r0+8)*20+c0];
                af[im][2]=pA[r0*20+c0+4]; af[im][3]=pA[(r0+8)*20+c0+4];
            }
#pragma unroll
            for (int in = 0; in < 8; in++){
                const int nn = wn*64 + in*8 + q;
                uint32_t b0 = pB[c0*136+nn], b1 = pB[(c0+4)*136+nn];
#pragma unroll
                for (int im = 0; im < 4; im++) mma8(acc[im][in], af[im], b0, b1);
            }
        }
        if (more) stage(buf ^ 1);
        __syncthreads();
    }
}

#define EPI(NI, ...) { const int lane=threadIdx.x&31, warp=threadIdx.x>>5; \
    const int wm=warp>>2, wn=warp&3; \
    _Pragma("unroll") for(int im=0;im<4;im++){ \
    _Pragma("unroll") for(int in=0;in<NI;in++){ \
    _Pragma("unroll") for(int h=0;h<2;h++){ \
    _Pragma("unroll") for(int g2=0;g2<2;g2++){ \
        const int row_l = wm*64+im*16+(lane>>2)+h*8; \
        const int col_l = wn*(NI*8)+in*8+(lane&3)*2+g2; \
        const float val = acc[im][in][h*2+g2]; __VA_ARGS__ }}}}}

#define EPI2(NI, ...) { const int lane=threadIdx.x&31, warp=threadIdx.x>>5; \
    const int wm=warp>>1, wn=warp&1; \
    _Pragma("unroll") for(int im=0;im<4;im++){ \
    _Pragma("unroll") for(int in=0;in<NI;in++){ \
    _Pragma("unroll") for(int h=0;h<2;h++){ \
    _Pragma("unroll") for(int g2=0;g2<2;g2++){ \
        const int row_l = wm*64+im*16+(lane>>2)+h*8; \
        const int col_l = wn*(NI*8)+in*8+(lane&3)*2+g2; \
        const float val = acc[im][in][h*2+g2]; __VA_ARGS__ }}}}}

#define SMW_NT   (2*(128*20) + 2*(128*20))
#define SMW_NN2  (2*(128*20) + 2*(16*72))
#define SMW_P128 (2*(128*20) + 2*(16*72))
#define SMW_GUF  (2*(128*20) + 4*(16*72))
#define SMW_DWN  (2*(128*20) + 2*(16*136))

// ---- GEMM kernels ----
__global__ void __launch_bounds__(128,3) k_qkv(
    const float* __restrict__ qw, const float* __restrict__ qb,
    const float* __restrict__ kw, const float* __restrict__ kb,
    const float* __restrict__ vw, const float* __restrict__ vb)
{
    __shared__ uint32_t sm[SMW_P128];
    const int tile = blockIdx.x, rm = blockIdx.y*128;
    const float* W; const float* bias; float* out; int ldo, bn;
    if (tile<16)      { W=qw; bias=qb; out=g_q; ldo=1024; bn=tile*64; }
    else if (tile<20) { W=kw; bias=kb; out=g_k; ldo=256;  bn=(tile-16)*64; }
    else              { W=vw; bias=vb; out=g_v; ldo=256;  bn=(tile-20)*64; }
    float acc[4][4][4];
    mm1_128(acc, g_h, HD, rm, W, ldo, bn, HD, sm, sm + 2*(128*20));
    EPI2(4, out[(size_t)(rm+row_l)*ldo + bn+col_l] = val + bias[bn+col_l]; )
}

__global__ void __launch_bounds__(128,3) k_oproj(
    const float* __restrict__ ow, const float* __restrict__ ob,
    const float* __restrict__ x)
{
    __shared__ uint32_t sm[SMW_P128];
    const int bn = blockIdx.x*64, rm = blockIdx.y*128;
    float acc[4][4][4];
    mm1_128(acc, g_ao, 1024, rm, ow, HD, bn, 1024, sm, sm + 2*(128*20));
    EPI2(4, { const int r = rm+row_l; const int c = bn+col_l;
              g_x2[(size_t)r*HD + c] = val + ob[c] + x[(size_t)r*HD + c]; } )
}

__global__ void __launch_bounds__(256,2) k_scores()
{
    __shared__ uint32_t sm[SMW_NT];
    const int bh = blockIdx.z, b = bh>>4, h = bh&15, hk = h>>2;
    const int rm = blockIdx.y*128, bn = blockIdx.x*128;
    const float* Q  = g_q + (size_t)b*SEQ*1024 + h*64;
    const float* Kp = g_k + (size_t)b*SEQ*256 + hk*64;
    float acc[4][4][4];
    mm_loop<4,true>(acc, Q, 1024, rm, Kp, 256, bn, 64, sm, sm + 2*(128*20));
    float* o = g_sc + ((size_t)bh*SEQ + rm)*SEQ + bn;
    EPI(4, o[(size_t)row_l*SEQ + col_l] = val*0.125f; )
}

__global__ void __launch_bounds__(256,2) k_pv()
{
    __shared__ uint32_t sm[SMW_NN2];
    const int bh = blockIdx.y, b = bh>>4, h = bh&15, hk = h>>2;
    const int rm = blockIdx.x*128;
    const float* P = g_sc + (size_t)bh*SEQ*SEQ;
    const float* V = g_v + (size_t)b*SEQ*256 + hk*64;
    float acc[4][2][4];
    mm_loop<2,false>(acc, P, SEQ, rm, V, 256, 0, SEQ, sm, sm + 2*(128*20));
    float* o = g_ao + (size_t)(b*SEQ + rm)*1024 + h*64;
    EPI(2, o[(size_t)row_l*1024 + col_l] = val; )
}

// fused gate+up with silu epilogue: 256 thr, tile 128x64, warp 32x32
__global__ void __launch_bounds__(256,2) k_guf(
    const float* __restrict__ gw, const float* __restrict__ uw,
    const float* __restrict__ gb, const float* __restrict__ ub)
{
    const int e = blockIdx.z, cnt = g_cnt[e], rm = blockIdx.y*128;
    if (rm >= cnt) return;
    __shared__ uint32_t smg[SMW_GUF];
    uint32_t* As = smg;
    uint32_t* B1 = smg + 2*(128*20);
    uint32_t* B2 = B1 + 2*(16*72);
    __shared__ int srow[128];
    if (threadIdx.x < 128){
        int rr = rm + threadIdx.x;
        srow[threadIdx.x] = (rr < cnt) ? g_rows[e*TB + rr] : 0;
    }
    __syncthreads();
    const int bn = blockIdx.x*64;
    float a1[2][4][4], a2[2][4][4];
    mm_dual256(a1, a2, g_t, HD, srow,
               gw + (size_t)e*HD*ID, uw + (size_t)e*HD*ID, ID, bn, HD, As, B1, B2);
    {
        const int lane = threadIdx.x&31, warp = threadIdx.x>>5;
        const int wm = warp>>1, wn = warp&1;
#pragma unroll
        for (int im = 0; im < 2; im++)
#pragma unroll
            for (int in = 0; in < 4; in++)
#pragma unroll
                for (int h = 0; h < 2; h++)
#pragma unroll
                    for (int g2 = 0; g2 < 2; g2++){
                        const int r = rm + wm*32+im*16+(lane>>2)+h*8;
                        if (r >= cnt) continue;
                        const int c = bn + wn*32+in*8+(lane&3)*2+g2;
                        float g = a1[im][in][h*2+g2] + gb[(size_t)e*ID + c];
                        float u = a2[im][in][h*2+g2] + ub[(size_t)e*ID + c];
                        g_act[((size_t)e*TB + r)*ID + c] = (g/(1.f+__expf(-g)))*u;
                    }
    }
}

__global__ void __launch_bounds__(128,2) k_down(const float* __restrict__ dw,
                                                const float* __restrict__ db)
{
    const int e = blockIdx.z, cnt = g_cnt[e], rm = blockIdx.y*128;
    if (rm >= cnt) return;
    __shared__ uint32_t sm[SMW_DWN];
    const int bn = blockIdx.x*128;
    float acc[4][8][4];
    mm_down(acc, g_act + (size_t)e*TB*ID, ID, rm,
            dw + (size_t)e*ID*HD, HD, bn, ID, sm, sm + 2*(128*20));
    EPI2(8, { const int r = rm+row_l;
              if (r < cnt){
                  const int c = bn+col_l;
                  g_dn[((size_t)e*TB + r)*HD + c] = val + db[(size_t)e*HD + c];
              } } )
}

// ---- elementwise / small kernels ----
__global__ void k_dummy(){}

__device__ __forceinline__ void rms_body(const float* __restrict__ x,
    const float* __restrict__ w, float* __restrict__ o)
{
    const int t = blockIdx.x, tid = threadIdx.x;
    const float* xr = x + (size_t)t*HD;
    float s = 0.f;
    for (int i = tid; i < HD; i += 256){ float v = xr[i]; s += v*v; }
    __shared__ float red[256];
    red[tid] = s; __syncthreads();
    for (int st = 128; st > 0; st >>= 1){ if (tid < st) red[tid] += red[tid+st]; __syncthreads(); }
    const float inv = rsqrtf(red[0]*(1.f/1024.f) + 1.1920929e-07f);
    for (int i = tid; i < HD; i += 256)
        o[(size_t)t*HD + i] = xr[i]*inv*w[i];
}
__global__ void __launch_bounds__(256) k_rms1(const float* x, const float* w){ rms_body(x, w, g_h); }
__global__ void __launch_bounds__(256) k_rms2(const float* w){ rms_body(g_x2, w, g_t); }

__global__ void __launch_bounds__(256) k_softmax()
{
    const int row = blockIdx.x*8 + (threadIdx.x>>5), lane = threadIdx.x&31;
    float4* p = (float4*)(g_sc + (size_t)row*SEQ);
    float4 v[4]; float mx = -3.402823e38f;
#pragma unroll
    for (int i=0;i<4;i++){ v[i]=p[lane+32*i];
        mx = fmaxf(mx, fmaxf(fmaxf(v[i].x,v[i].y), fmaxf(v[i].z,v[i].w))); }
#pragma unroll
    for (int o=16;o>0;o>>=1) mx = fmaxf(mx, __shfl_xor_sync(~0u, mx, o));
    float sum = 0.f;
#pragma unroll
    for (int i=0;i<4;i++){
        v[i].x=__expf(v[i].x-mx); v[i].y=__expf(v[i].y-mx);
        v[i].z=__expf(v[i].z-mx); v[i].w=__expf(v[i].w-mx);
        sum += v[i].x+v[i].y+v[i].z+v[i].w; }
#pragma unroll
    for (int o=16;o>0;o>>=1) sum += __shfl_xor_sync(~0u, sum, o);
    const float inv = 1.f/sum;
#pragma unroll
    for (int i=0;i<4;i++){ v[i].x*=inv; v[i].y*=inv; v[i].z*=inv; v[i].w*=inv; p[lane+32*i]=v[i]; }
}

__global__ void k_zero(){ if (threadIdx.x < NE) g_cnt[threadIdx.x] = 0; }

__global__ void __launch_bounds__(256) k_router(const float* __restrict__ rw,
    const float* __restrict__ rb)
{
    const int t = blockIdx.x, tid = threadIdx.x;
    const float* x = g_t + (size_t)t*HD;
    const int e = tid & 7, ch = tid >> 3;
    float s = 0.f;
    for (int i = ch*32; i < ch*32+32; i++) s += x[i]*rw[i*NE + e];
    __shared__ float part[32][9];
    __shared__ float sl[8];
    part[ch][e] = s; __syncthreads();
    if (tid < 8){
        float l = rb[tid];
        for (int c2 = 0; c2 < 32; c2++) l += part[c2][tid];
        sl[tid] = l;
    }
    __syncthreads();
    if (tid == 0){
        int e0 = 0; float v0 = sl[0];
        for (int i = 1; i < 8; i++) if (sl[i] > v0){ v0 = sl[i]; e0 = i; }
        int e1 = -1; float v1 = -3.402823e38f;
        for (int i = 0; i < 8; i++){ if (i == e0) continue; if (sl[i] > v1){ v1 = sl[i]; e1 = i; } }
        const float z = __expf(v1 - v0);
        const float p0 = 1.f/(1.f+z), p1 = z/(1.f+z);
        const int r0 = atomicAdd(&g_cnt[e0], 1);
        const int r1 = atomicAdd(&g_cnt[e1], 1);
        g_rows[e0*TB + r0] = t; g_rows[e1*TB + r1] = t;
        g_se[t*2+0] = e0; g_sr[t*2+0] = r0; g_sp[t*2+0] = p0;
        g_se[t*2+1] = e1; g_sr[t*2+1] = r1; g_sp[t*2+1] = p1;
    }
}

__global__ void __launch_bounds__(256) k_combine(float* __restrict__ out)
{
    const int t = blockIdx.x, tid = threadIdx.x;
    const int e0 = g_se[t*2+0], r0 = g_sr[t*2+0];
    const int e1 = g_se[t*2+1], r1 = g_sr[t*2+1];
    const float p0 = g_sp[t*2+0], p1 = g_sp[t*2+1];
    const float* d0 = g_dn + ((size_t)e0*TB + r0)*HD;
    const float* d1 = g_dn + ((size_t)e1*TB + r1)*HD;
    const float* xr = g_x2 + (size_t)t*HD;
    for (int i = tid; i < HD; i += 256)
        out[(size_t)t*HD + i] = xr[i] + p0*d0[i] + p1*d1[i];
}

// ---- launcher ----
extern "C" void kernel_launch(void* const* d_in, const int* in_sizes, int n_in,
                              void* d_out, int out_size)
{
    (void)in_sizes; (void)n_in; (void)out_size;
    const float* x   = (const float*)d_in[0];
    const float* n1w = (const float*)d_in[1];
    const float* qw  = (const float*)d_in[2];
    const float* qb  = (const float*)d_in[3];
    const float* kw  = (const float*)d_in[4];
    const float* kb  = (const float*)d_in[5];
    const float* vw  = (const float*)d_in[6];
    const float* vb  = (const float*)d_in[7];
    const float* ow  = (const float*)d_in[8];
    const float* ob  = (const float*)d_in[9];
    const float* n2w = (const float*)d_in[10];
    const float* rw  = (const float*)d_in[11];
    const float* rb  = (const float*)d_in[12];
    const float* gw  = (const float*)d_in[13];
    const float* gb  = (const float*)d_in[14];
    const float* uw  = (const float*)d_in[15];
    const float* ub  = (const float*)d_in[16];
    const float* dw  = (const float*)d_in[17];
    const float* db  = (const float*)d_in[18];
    float* out = (float*)d_out;

    // launches 1-3 (independent) so that launch #4 = k_qkv gets the ncu capture
    k_zero<<<1, 32>>>();
    k_rms1<<<TB, 256>>>(x, n1w);
    k_dummy<<<1, 32>>>();
    k_qkv<<<dim3(24, 8), 128>>>(qw, qb, kw, kb, vw, vb);
    k_scores<<<dim3(4, 4, NB*NHQ), 256>>>();
    k_softmax<<<NB*NHQ*SEQ/8, 256>>>();
    k_pv<<<dim3(4, NB*NHQ), 256>>>();
    k_oproj<<<dim3(16, 8), 128>>>(ow, ob, x);
    k_rms2<<<TB, 256>>>(n2w);
    k_router<<<TB, 256>>>(rw, rb);
    k_guf<<<dim3(ID/64, 8, NE), 256>>>(gw, uw, gb, ub);
    k_down<<<dim3(HD/128, 8, NE), 128>>>(dw, db);
    k_combine<<<TB, 256>>>(out);
}

// round 17
// speedup vs baseline: 1.5078x; 1.5078x over previous
#include <cuda_runtime.h>
#include <math.h>
#include <stdint.h>

#define TB 1024
#define HD 1024
#define NHQ 16
#define NHKV 4
#define DH 64
#define SEQ 512
#define NB 2
#define NE 8
#define ID 4096

// ---- scratch ----
__device__ float g_h [TB*HD + 16];
__device__ float g_q [TB*NHQ*DH + 16];
__device__ float g_k [TB*NHKV*DH + 16];
__device__ float g_v [TB*NHKV*DH + 16];
__device__ float g_sc[(size_t)NB*NHQ*SEQ*SEQ + 16];
__device__ float g_ao[TB*NHQ*DH + 16];
__device__ float g_x2[TB*HD + 16];
__device__ float g_t [TB*HD + 16];
__device__ int   g_cnt[NE];
__device__ int   g_rows[NE*TB];
__device__ int   g_se[TB*2];
__device__ int   g_sr[TB*2];
__device__ float g_sp[TB*2];
__device__ float g_act[(size_t)NE*TB*ID + 16];
__device__ float g_dn [(size_t)NE*TB*HD + 16];

// ---- primitives ----
__device__ __forceinline__ uint32_t tf32cvt(float x){
    uint32_t u; asm("cvt.rna.tf32.f32 %0, %1;" : "=r"(u) : "f"(x)); return u;
}
__device__ __forceinline__ uint4 cvt4(float4 v){
    return make_uint4(tf32cvt(v.x), tf32cvt(v.y), tf32cvt(v.z), tf32cvt(v.w));
}
__device__ __forceinline__ void mma8(float* d, const uint32_t* a, uint32_t b0, uint32_t b1){
    asm volatile("mma.sync.aligned.m16n8k8.row.col.f32.tf32.tf32.f32 "
        "{%0,%1,%2,%3},{%4,%5,%6,%7},{%8,%9},{%0,%1,%2,%3};"
        : "+f"(d[0]),"+f"(d[1]),"+f"(d[2]),"+f"(d[3])
        : "r"(a[0]),"r"(a[1]),"r"(a[2]),"r"(a[3]),"r"(b0),"r"(b1));
}

// ============ tf32 MMA mainloop (templated), 256 thr ============
template<int NI, bool BTRANS, bool GATHER>
__device__ __forceinline__ void mm_loop(float (&acc)[4][NI][4],
    const float* __restrict__ A, int lda, const int* srow, int rm,
    const float* __restrict__ B, int ldb, int bn, int K,
    uint32_t* As, uint32_t* Bs)
{
    const int BPITCH = BTRANS ? 20 : NI*32 + 8;
    const int ASTG = 128*20;
    const int BSTG = BTRANS ? 128*20 : 16*BPITCH;
    const int tid = threadIdx.x, lane = tid & 31, warp = tid >> 5;
    const int wm = warp >> 2, wn = warp & 3, q = lane >> 2, s = lane & 3;
#pragma unroll
    for (int i = 0; i < 4; i++)
#pragma unroll
        for (int j = 0; j < NI; j++)
#pragma unroll
            for (int r = 0; r < 4; r++) acc[i][j][r] = 0.f;

    const int f0 = tid, f1 = tid + 256;
    const int ar0 = f0 >> 2, ac0 = (f0 & 3) << 2;
    const int ar1 = f1 >> 2, ac1 = (f1 & 3) << 2;
    const int ga0 = GATHER ? srow[ar0] : rm + ar0;
    const int ga1 = GATHER ? srow[ar1] : rm + ar1;
    const float* pa0 = A + (size_t)ga0*lda + ac0;
    const float* pa1 = A + (size_t)ga1*lda + ac1;

    const float* pb0; const float* pb1 = nullptr;
    int bs0, bs1 = 0;
    if (BTRANS){
        pb0 = B + (size_t)(bn + ar0)*ldb + ac0;
        pb1 = B + (size_t)(bn + ar1)*ldb + ac1;
        bs0 = ar0*20 + ac0; bs1 = ar1*20 + ac1;
    } else if (NI == 4){
        const int bk0 = f0 >> 5, bc0 = (f0 & 31) << 2;
        const int bk1 = f1 >> 5, bc1 = (f1 & 31) << 2;
        pb0 = B + (size_t)bk0*ldb + bn + bc0;
        pb1 = B + (size_t)bk1*ldb + bn + bc1;
        bs0 = bk0*BPITCH + bc0; bs1 = bk1*BPITCH + bc1;
    } else {
        const int bk0 = tid >> 4, bc0 = (tid & 15) << 2;
        pb0 = B + (size_t)bk0*ldb + bn + bc0;
        bs0 = bk0*BPITCH + bc0;
    }

    float4 va0, va1, vb0, vb1;
    auto gload = [&](int k0){
        va0 = *(const float4*)(pa0 + k0);
        va1 = *(const float4*)(pa1 + k0);
        if (BTRANS){
            vb0 = *(const float4*)(pb0 + k0);
            vb1 = *(const float4*)(pb1 + k0);
        } else {
            vb0 = *(const float4*)(pb0 + (size_t)k0*ldb);
            if (NI == 4) vb1 = *(const float4*)(pb1 + (size_t)k0*ldb);
        }
    };
    auto stage = [&](int buf){
        uint32_t* dA = As + buf*ASTG;
        *(uint4*)(dA + ar0*20 + ac0) = cvt4(va0);
        *(uint4*)(dA + ar1*20 + ac1) = cvt4(va1);
        uint32_t* dB = Bs + buf*BSTG;
        *(uint4*)(dB + bs0) = cvt4(vb0);
        if (BTRANS || NI == 4) *(uint4*)(dB + bs1) = cvt4(vb1);
    };

    gload(0); stage(0); __syncthreads();
    const int nst = K >> 4;
    for (int st = 0; st < nst; st++){
        const int buf = st & 1;
        const bool more = (st + 1 < nst);
        if (more) gload((st + 1) << 4);
        const uint32_t* pA = As + buf*ASTG;
        const uint32_t* pB = Bs + buf*BSTG;
#pragma unroll
        for (int kk = 0; kk < 2; kk++){
            const int c0 = kk*8 + s;
            uint32_t af[4][4];
#pragma unroll
            for (int im = 0; im < 4; im++){
                const int r0 = wm*64 + im*16 + q;
                af[im][0]=pA[r0*20+c0];   af[im][1]=pA[(r0+8)*20+c0];
                af[im][2]=pA[r0*20+c0+4]; af[im][3]=pA[(r0+8)*20+c0+4];
            }
#pragma unroll
            for (int in = 0; in < NI; in++){
                const int nn = wn*(NI*8) + in*8 + q;
                uint32_t b0, b1;
                if (BTRANS){ b0 = pB[nn*20+c0]; b1 = pB[nn*20+c0+4]; }
                else       { b0 = pB[c0*BPITCH+nn]; b1 = pB[(c0+4)*BPITCH+nn]; }
#pragma unroll
                for (int im = 0; im < 4; im++) mma8(acc[im][in], af[im], b0, b1);
            }
        }
        if (more) stage(buf ^ 1);
        __syncthreads();
    }
}

// ===== dual-B mainloop, 128 thr, tile 128x64, warp 64x32 (2 CTAs/SM) =====
__device__ __forceinline__ void mm_dual128(float (&a1)[4][4][4], float (&a2)[4][4][4],
    const float* __restrict__ A, int lda, const int* srow,
    const float* __restrict__ B1, const float* __restrict__ B2,
    int ldb, int bn, int K,
    uint32_t* As, uint32_t* B1s, uint32_t* B2s)
{
    const int ASTG = 128*20, BSTG = 16*72;
    const int tid = threadIdx.x, lane = tid & 31, warp = tid >> 5;
    const int wm = warp >> 1, wn = warp & 1, q = lane >> 2, s = lane & 3;
#pragma unroll
    for (int i = 0; i < 4; i++)
#pragma unroll
        for (int j = 0; j < 4; j++)
#pragma unroll
            for (int r = 0; r < 4; r++){ a1[i][j][r]=0.f; a2[i][j][r]=0.f; }

    int ar[4], ac[4];
    const float* pa[4];
#pragma unroll
    for (int i = 0; i < 4; i++){
        const int f = tid + i*128;
        ar[i] = f >> 2; ac[i] = (f & 3) << 2;
        pa[i] = A + (size_t)srow[ar[i]]*lda + ac[i];
    }
    int bs[2];
    const float* p1[2]; const float* p2[2];
#pragma unroll
    for (int i = 0; i < 2; i++){
        const int f = tid + i*128;
        const int bk = f >> 4, bc = (f & 15) << 2;
        bs[i] = bk*72 + bc;
        p1[i] = B1 + (size_t)bk*ldb + bn + bc;
        p2[i] = B2 + (size_t)bk*ldb + bn + bc;
    }

    float4 va[4], w1[2], w2[2];
    auto gload = [&](int k0){
#pragma unroll
        for (int i = 0; i < 2; i++){
            w1[i] = *(const float4*)(p1[i] + (size_t)k0*ldb);
            w2[i] = *(const float4*)(p2[i] + (size_t)k0*ldb);
        }
#pragma unroll
        for (int i = 0; i < 4; i++) va[i] = *(const float4*)(pa[i] + k0);
    };
    auto stage = [&](int buf){
        uint32_t* dA = As + buf*ASTG;
#pragma unroll
        for (int i = 0; i < 4; i++)
            *(uint4*)(dA + ar[i]*20 + ac[i]) = cvt4(va[i]);
        uint32_t* d1 = B1s + buf*BSTG;
        uint32_t* d2 = B2s + buf*BSTG;
#pragma unroll
        for (int i = 0; i < 2; i++){
            *(uint4*)(d1 + bs[i]) = cvt4(w1[i]);
            *(uint4*)(d2 + bs[i]) = cvt4(w2[i]);
        }
    };

    gload(0); stage(0); __syncthreads();
    const int nst = K >> 4;
    for (int st = 0; st < nst; st++){
        const int buf = st & 1;
        const bool more = (st + 1 < nst);
        if (more) gload((st + 1) << 4);
        const uint32_t* pA = As + buf*ASTG;
        const uint32_t* q1 = B1s + buf*BSTG;
        const uint32_t* q2 = B2s + buf*BSTG;
#pragma unroll
        for (int kk = 0; kk < 2; kk++){
            const int c0 = kk*8 + s;
            uint32_t af[4][4];
#pragma unroll
            for (int im = 0; im < 4; im++){
                const int r0 = wm*64 + im*16 + q;
                af[im][0]=pA[r0*20+c0];   af[im][1]=pA[(r0+8)*20+c0];
                af[im][2]=pA[r0*20+c0+4]; af[im][3]=pA[(r0+8)*20+c0+4];
            }
#pragma unroll
            for (int in = 0; in < 4; in++){
                const int nn = wn*32 + in*8 + q;
                uint32_t b0 = q1[c0*72+nn], b1 = q1[(c0+4)*72+nn];
                uint32_t c0b = q2[c0*72+nn], c1b = q2[(c0+4)*72+nn];
#pragma unroll
                for (int im = 0; im < 4; im++){
                    mma8(a1[im][in], af[im], b0, b1);
                    mma8(a2[im][in], af[im], c0b, c1b);
                }
            }
        }
        if (more) stage(buf ^ 1);
        __syncthreads();
    }
}

// ============ 4-warp (128 thr) warp-64x64 mainloop for k_down ============
__device__ __forceinline__ void mm_down(float (&acc)[4][8][4],
    const float* __restrict__ A, int lda, int rm,
    const float* __restrict__ B, int ldb, int bn, int K,
    uint32_t* As, uint32_t* Bs)
{
    const int ASTG = 128*20, BSTG = 16*136;
    const int tid = threadIdx.x, lane = tid & 31, warp = tid >> 5;
    const int wm = warp >> 1, wn = warp & 1, q = lane >> 2, s = lane & 3;
#pragma unroll
    for (int i = 0; i < 4; i++)
#pragma unroll
        for (int j = 0; j < 8; j++)
#pragma unroll
            for (int r = 0; r < 4; r++) acc[i][j][r] = 0.f;

    int ar[4], ac[4], bs[4];
    const float* pa[4]; const float* pb[4];
#pragma unroll
    for (int i = 0; i < 4; i++){
        const int f = tid + i*128;
        ar[i] = f >> 2; ac[i] = (f & 3) << 2;
        pa[i] = A + (size_t)(rm + ar[i])*lda + ac[i];
        const int bk = f >> 5, bc = (f & 31) << 2;
        bs[i] = bk*136 + bc;
        pb[i] = B + (size_t)bk*ldb + bn + bc;
    }

    float4 va[4], vb[4];
    auto gload = [&](int k0){
#pragma unroll
        for (int i = 0; i < 4; i++){
            va[i] = *(const float4*)(pa[i] + k0);
            vb[i] = *(const float4*)(pb[i] + (size_t)k0*ldb);
        }
    };
    auto stage = [&](int buf){
        uint32_t* dA = As + buf*ASTG;
        uint32_t* dB = Bs + buf*BSTG;
#pragma unroll
        for (int i = 0; i < 4; i++){
            *(uint4*)(dA + ar[i]*20 + ac[i]) = cvt4(va[i]);
            *(uint4*)(dB + bs[i]) = cvt4(vb[i]);
        }
    };

    gload(0); stage(0); __syncthreads();
    const int nst = K >> 4;
    for (int st = 0; st < nst; st++){
        const int buf = st & 1;
        const bool more = (st + 1 < nst);
        if (more) gload((st + 1) << 4);
        const uint32_t* pA = As + buf*ASTG;
        const uint32_t* pB = Bs + buf*BSTG;
#pragma unroll
        for (int kk = 0; kk < 2; kk++){
            const int c0 = kk*8 + s;
            uint32_t af[4][4];
#pragma unroll
            for (int im = 0; im < 4; im++){
                const int r0 = wm*64 + im*16 + q;
                af[im][0]=pA[r0*20+c0];   af[im][1]=pA[(r0+8)*20+c0];
                af[im][2]=pA[r0*20+c0+4]; af[im][3]=pA[(r0+8)*20+c0+4];
            }
#pragma unroll
            for (int in = 0; in < 8; in++){
                const int nn = wn*64 + in*8 + q;
                uint32_t b0 = pB[c0*136+nn], b1 = pB[(c0+4)*136+nn];
#pragma unroll
                for (int im = 0; im < 4; im++) mma8(acc[im][in], af[im], b0, b1);
            }
        }
        if (more) stage(buf ^ 1);
        __syncthreads();
    }
}

#define EPI(NI, ...) { const int lane=threadIdx.x&31, warp=threadIdx.x>>5; \
    const int wm=warp>>2, wn=warp&3; \
    _Pragma("unroll") for(int im=0;im<4;im++){ \
    _Pragma("unroll") for(int in=0;in<NI;in++){ \
    _Pragma("unroll") for(int h=0;h<2;h++){ \
    _Pragma("unroll") for(int g2=0;g2<2;g2++){ \
        const int row_l = wm*64+im*16+(lane>>2)+h*8; \
        const int col_l = wn*(NI*8)+in*8+(lane&3)*2+g2; \
        const float val = acc[im][in][h*2+g2]; __VA_ARGS__ }}}}}

#define EPI2(NI, ...) { const int lane=threadIdx.x&31, warp=threadIdx.x>>5; \
    const int wm=warp>>1, wn=warp&1; \
    _Pragma("unroll") for(int im=0;im<4;im++){ \
    _Pragma("unroll") for(int in=0;in<NI;in++){ \
    _Pragma("unroll") for(int h=0;h<2;h++){ \
    _Pragma("unroll") for(int g2=0;g2<2;g2++){ \
        const int row_l = wm*64+im*16+(lane>>2)+h*8; \
        const int col_l = wn*(NI*8)+in*8+(lane&3)*2+g2; \
        const float val = acc[im][in][h*2+g2]; __VA_ARGS__ }}}}}

#define SMW_NN4 (2*(128*20) + 2*(16*136))
#define SMW_NT  (2*(128*20) + 2*(128*20))
#define SMW_NN2 (2*(128*20) + 2*(16*72))
#define SMW_GUF (2*(128*20) + 4*(16*72))

// ---- GEMM kernels ----
__global__ void __launch_bounds__(256,2) k_qkv(
    const float* __restrict__ qw, const float* __restrict__ qb,
    const float* __restrict__ kw, const float* __restrict__ kb,
    const float* __restrict__ vw, const float* __restrict__ vb)
{
    __shared__ uint32_t sm[SMW_NN4];
    const int tile = blockIdx.x, rm = blockIdx.y*128;
    const float* W; const float* bias; float* out; int ldo, bn;
    if (tile<8)       { W=qw; bias=qb; out=g_q; ldo=1024; bn=tile*128; }
    else if (tile<10) { W=kw; bias=kb; out=g_k; ldo=256;  bn=(tile-8)*128; }
    else              { W=vw; bias=vb; out=g_v; ldo=256;  bn=(tile-10)*128; }
    float acc[4][4][4];
    mm_loop<4,false,false>(acc, g_h, HD, nullptr, rm, W, ldo, bn, HD, sm, sm + 2*(128*20));
    EPI(4, out[(size_t)(rm+row_l)*ldo + bn+col_l] = val + bias[bn+col_l]; )
}

__global__ void __launch_bounds__(256,2) k_scores()
{
    __shared__ uint32_t sm[SMW_NT];
    const int bh = blockIdx.z, b = bh>>4, h = bh&15, hk = h>>2;
    const int rm = blockIdx.y*128, bn = blockIdx.x*128;
    const float* Q  = g_q + (size_t)b*SEQ*1024 + h*64;
    const float* Kp = g_k + (size_t)b*SEQ*256 + hk*64;
    float acc[4][4][4];
    mm_loop<4,true,false>(acc, Q, 1024, nullptr, rm, Kp, 256, bn, 64, sm, sm + 2*(128*20));
    float* o = g_sc + ((size_t)bh*SEQ + rm)*SEQ + bn;
    EPI(4, o[(size_t)row_l*SEQ + col_l] = val*0.125f; )
}

__global__ void __launch_bounds__(256,2) k_pv()
{
    __shared__ uint32_t sm[SMW_NN2];
    const int bh = blockIdx.y, b = bh>>4, h = bh&15, hk = h>>2;
    const int rm = blockIdx.x*128;
    const float* P = g_sc + (size_t)bh*SEQ*SEQ;
    const float* V = g_v + (size_t)b*SEQ*256 + hk*64;
    float acc[4][2][4];
    mm_loop<2,false,false>(acc, P, SEQ, nullptr, rm, V, 256, 0, SEQ, sm, sm + 2*(128*20));
    float* o = g_ao + (size_t)(b*SEQ + rm)*1024 + h*64;
    EPI(2, o[(size_t)row_l*1024 + col_l] = val; )
}

__global__ void __launch_bounds__(256,2) k_oproj(
    const float* __restrict__ ow, const float* __restrict__ ob,
    const float* __restrict__ x)
{
    __shared__ uint32_t sm[SMW_NN4];
    const int bn = blockIdx.x*128, rm = blockIdx.y*128;
    float acc[4][4][4];
    mm_loop<4,false,false>(acc, g_ao, 1024, nullptr, rm, ow, HD, bn, 1024, sm, sm + 2*(128*20));
    EPI(4, { const int r = rm+row_l; const int c = bn+col_l;
             g_x2[(size_t)r*HD + c] = val + ob[c] + x[(size_t)r*HD + c]; } )
}

// fused gate+up with silu epilogue: 128 thr, tile 128x64
__global__ void __launch_bounds__(128,2) k_guf(
    const float* __restrict__ gw, const float* __restrict__ uw,
    const float* __restrict__ gb, const float* __restrict__ ub)
{
    const int e = blockIdx.z, cnt = g_cnt[e], rm = blockIdx.y*128;
    if (rm >= cnt) return;
    __shared__ uint32_t smg[SMW_GUF];
    uint32_t* As = smg;
    uint32_t* B1 = smg + 2*(128*20);
    uint32_t* B2 = B1 + 2*(16*72);
    __shared__ int srow[128];
    if (threadIdx.x < 128){
        int rr = rm + threadIdx.x;
        srow[threadIdx.x] = (rr < cnt) ? g_rows[e*TB + rr] : 0;
    }
    __syncthreads();
    const int bn = blockIdx.x*64;
    float a1[4][4][4], a2[4][4][4];
    mm_dual128(a1, a2, g_t, HD, srow,
               gw + (size_t)e*HD*ID, uw + (size_t)e*HD*ID, ID, bn, HD, As, B1, B2);
    {
        const int lane = threadIdx.x&31, warp = threadIdx.x>>5;
        const int wm = warp>>1, wn = warp&1;
#pragma unroll
        for (int im = 0; im < 4; im++)
#pragma unroll
            for (int in = 0; in < 4; in++)
#pragma unroll
                for (int h = 0; h < 2; h++)
#pragma unroll
                    for (int g2 = 0; g2 < 2; g2++){
                        const int r = rm + wm*64+im*16+(lane>>2)+h*8;
                        if (r >= cnt) continue;
                        const int c = bn + wn*32+in*8+(lane&3)*2+g2;
                        float g = a1[im][in][h*2+g2] + gb[(size_t)e*ID + c];
                        float u = a2[im][in][h*2+g2] + ub[(size_t)e*ID + c];
                        g_act[((size_t)e*TB + r)*ID + c] = (g/(1.f+__expf(-g)))*u;
                    }
    }
}

__global__ void __launch_bounds__(128,2) k_down(const float* __restrict__ dw,
                                                const float* __restrict__ db)
{
    const int e = blockIdx.z, cnt = g_cnt[e], rm = blockIdx.y*128;
    if (rm >= cnt) return;
    __shared__ uint32_t sm[SMW_NN4];
    const int bn = blockIdx.x*128;
    float acc[4][8][4];
    mm_down(acc, g_act + (size_t)e*TB*ID, ID, rm,
            dw + (size_t)e*ID*HD, HD, bn, ID, sm, sm + 2*(128*20));
    EPI2(8, { const int r = rm+row_l;
              if (r < cnt){
                  const int c = bn+col_l;
                  g_dn[((size_t)e*TB + r)*HD + c] = val + db[(size_t)e*HD + c];
              } } )
}

// ---- elementwise / small kernels ----
__global__ void k_dummy(){}

__device__ __forceinline__ void rms_body(const float* __restrict__ x,
    const float* __restrict__ w, float* __restrict__ o)
{
    const int t = blockIdx.x, tid = threadIdx.x;
    const float4* xr = (const float4*)(x + (size_t)t*HD);
    float4 v = xr[tid];
    float s = v.x*v.x + v.y*v.y + v.z*v.z + v.w*v.w;
#pragma unroll
    for (int off = 16; off > 0; off >>= 1) s += __shfl_xor_sync(~0u, s, off);
    __shared__ float red[8];
    if ((tid & 31) == 0) red[tid >> 5] = s;
    __syncthreads();
    if (tid < 8){
        float r2 = red[tid];
#pragma unroll
        for (int off = 4; off > 0; off >>= 1) r2 += __shfl_xor_sync(0xFFu, r2, off);
        red[tid] = r2;
    }
    __syncthreads();
    const float inv = rsqrtf(red[0]*(1.f/1024.f) + 1.1920929e-07f);
    const float4 wv = ((const float4*)w)[tid];
    float4 ov;
    ov.x = v.x*inv*wv.x; ov.y = v.y*inv*wv.y;
    ov.z = v.z*inv*wv.z; ov.w = v.w*inv*wv.w;
    ((float4*)(o + (size_t)t*HD))[tid] = ov;
}
__global__ void __launch_bounds__(256) k_rms1(const float* x, const float* w){ rms_body(x, w, g_h); }
__global__ void __launch_bounds__(256) k_rms2(const float* w){ rms_body(g_x2, w, g_t); }

__global__ void __launch_bounds__(256) k_softmax()
{
    const int row = blockIdx.x*8 + (threadIdx.x>>5), lane = threadIdx.x&31;
    float4* p = (float4*)(g_sc + (size_t)row*SEQ);
    float4 v[4]; float mx = -3.402823e38f;
#pragma unroll
    for (int i=0;i<4;i++){ v[i]=p[lane+32*i];
        mx = fmaxf(mx, fmaxf(fmaxf(v[i].x,v[i].y), fmaxf(v[i].z,v[i].w))); }
#pragma unroll
    for (int o=16;o>0;o>>=1) mx = fmaxf(mx, __shfl_xor_sync(~0u, mx, o));
    float sum = 0.f;
#pragma unroll
    for (int i=0;i<4;i++){
        v[i].x=__expf(v[i].x-mx); v[i].y=__expf(v[i].y-mx);
        v[i].z=__expf(v[i].z-mx); v[i].w=__expf(v[i].w-mx);
        sum += v[i].x+v[i].y+v[i].z+v[i].w; }
#pragma unroll
    for (int o=16;o>0;o>>=1) sum += __shfl_xor_sync(~0u, sum, o);
    const float inv = 1.f/sum;
#pragma unroll
    for (int i=0;i<4;i++){ v[i].x*=inv; v[i].y*=inv; v[i].z*=inv; v[i].w*=inv; p[lane+32*i]=v[i]; }
}

__global__ void k_zero(){ if (threadIdx.x < NE) g_cnt[threadIdx.x] = 0; }

__global__ void __launch_bounds__(256) k_router(const float* __restrict__ rw,
    const float* __restrict__ rb)
{
    const int t = blockIdx.x, tid = threadIdx.x;
    const float* x = g_t + (size_t)t*HD;
    const int e = tid & 7, ch = tid >> 3;
    float s = 0.f;
    for (int i = ch*32; i < ch*32+32; i++) s += x[i]*rw[i*NE + e];
    __shared__ float part[32][9];
    __shared__ float sl[8];
    part[ch][e] = s; __syncthreads();
    if (tid < 8){
        float l = rb[tid];
        for (int c2 = 0; c2 < 32; c2++) l += part[c2][tid];
        sl[tid] = l;
    }
    __syncthreads();
    if (tid == 0){
        int e0 = 0; float v0 = sl[0];
        for (int i = 1; i < 8; i++) if (sl[i] > v0){ v0 = sl[i]; e0 = i; }
        int e1 = -1; float v1 = -3.402823e38f;
        for (int i = 0; i < 8; i++){ if (i == e0) continue; if (sl[i] > v1){ v1 = sl[i]; e1 = i; } }
        const float z = __expf(v1 - v0);
        const float p0 = 1.f/(1.f+z), p1 = z/(1.f+z);
        const int r0 = atomicAdd(&g_cnt[e0], 1);
        const int r1 = atomicAdd(&g_cnt[e1], 1);
        g_rows[e0*TB + r0] = t; g_rows[e1*TB + r1] = t;
        g_se[t*2+0] = e0; g_sr[t*2+0] = r0; g_sp[t*2+0] = p0;
        g_se[t*2+1] = e1; g_sr[t*2+1] = r1; g_sp[t*2+1] = p1;
    }
}

__global__ void __launch_bounds__(256) k_combine(float* __restrict__ out)
{
    const int t = blockIdx.x, tid = threadIdx.x;
    const int e0 = g_se[t*2+0], r0 = g_sr[t*2+0];
    const int e1 = g_se[t*2+1], r1 = g_sr[t*2+1];
    const float p0 = g_sp[t*2+0], p1 = g_sp[t*2+1];
    const float4* d0 = (const float4*)(g_dn + ((size_t)e0*TB + r0)*HD);
    const float4* d1 = (const float4*)(g_dn + ((size_t)e1*TB + r1)*HD);
    const float4* xr = (const float4*)(g_x2 + (size_t)t*HD);
    float4 a = xr[tid], b = d0[tid], c = d1[tid];
    float4 o;
    o.x = a.x + p0*b.x + p1*c.x;
    o.y = a.y + p0*b.y + p1*c.y;
    o.z = a.z + p0*b.z + p1*c.z;
    o.w = a.w + p0*b.w + p1*c.w;
    ((float4*)(out + (size_t)t*HD))[tid] = o;
}

// ---- launcher ----
extern "C" void kernel_launch(void* const* d_in, const int* in_sizes, int n_in,
                              void* d_out, int out_size)
{
    (void)in_sizes; (void)n_in; (void)out_size;
    const float* x   = (const float*)d_in[0];
    const float* n1w = (const float*)d_in[1];
    const float* qw  = (const float*)d_in[2];
    const float* qb  = (const float*)d_in[3];
    const float* kw  = (const float*)d_in[4];
    const float* kb  = (const float*)d_in[5];
    const float* vw  = (const float*)d_in[6];
    const float* vb  = (const float*)d_in[7];
    const float* ow  = (const float*)d_in[8];
    const float* ob  = (const float*)d_in[9];
    const float* n2w = (const float*)d_in[10];
    const float* rw  = (const float*)d_in[11];
    const float* rb  = (const float*)d_in[12];
    const float* gw  = (const float*)d_in[13];
    const float* gb  = (const float*)d_in[14];
    const float* uw  = (const float*)d_in[15];
    const float* ub  = (const float*)d_in[16];
    const float* dw  = (const float*)d_in[17];
    const float* db  = (const float*)d_in[18];
    float* out = (float*)d_out;

    // launches 1-3 (independent) so that launch #4 = k_qkv gets the ncu capture
    k_zero<<<1, 32>>>();
    k_rms1<<<TB, 256>>>(x, n1w);
    k_dummy<<<1, 32>>>();
    k_qkv<<<dim3(12, 8), 256>>>(qw, qb, kw, kb, vw, vb);
    k_scores<<<dim3(4, 4, NB*NHQ), 256>>>();
    k_softmax<<<NB*NHQ*SEQ/8, 256>>>();
    k_pv<<<dim3(4, NB*NHQ), 256>>>();
    k_oproj<<<dim3(8, 8), 256>>>(ow, ob, x);
    k_rms2<<<TB, 256>>>(n2w);
    k_router<<<TB, 256>>>(rw, rb);
    k_guf<<<dim3(ID/64, 8, NE), 128>>>(gw, uw, gb, ub);
    k_down<<<dim3(HD/128, 8, NE), 128>>>(dw, db);
    k_combine<<<TB, 256>>>(out);
}